// round 14
// baseline (speedup 1.0000x reference)
#include <cuda_runtime.h>
#include <cuda_bf16.h>
#include <cstdint>

// TinyRNN (GRU): B=4096, T=2048, I=3, H=4, O=2
// 1 thread per batch element (all 4 hidden units local -> NO shuffles, short
// chain) with fma.rn.f32x2 packed gate math (12 gate columns -> 6 packed
// accumulators, halving the FMA-pipe cost that bound Round 9).
// 128 blocks x 32 threads = 128 warps; wall time = per-warp step cost.

#define BB 4096
#define TT 2048
#define CHUNK 32
#define THREADS 32

// ---- f32x2 helpers (sm_100 packed pairs) ----
__device__ __forceinline__ uint64_t pk2(float lo, float hi) {
    uint64_t r; asm("mov.b64 %0, {%1, %2};" : "=l"(r) : "f"(lo), "f"(hi)); return r;
}
__device__ __forceinline__ void upk2(float& lo, float& hi, uint64_t v) {
    asm("mov.b64 {%0, %1}, %2;" : "=f"(lo), "=f"(hi) : "l"(v));
}
__device__ __forceinline__ uint64_t fma2(uint64_t a, uint64_t b, uint64_t c) {
    uint64_t r; asm("fma.rn.f32x2 %0, %1, %2, %3;" : "=l"(r) : "l"(a), "l"(b), "l"(c)); return r;
}
__device__ __forceinline__ uint64_t add2(uint64_t a, uint64_t b) {
    uint64_t r; asm("add.rn.f32x2 %0, %1, %2;" : "=l"(r) : "l"(a), "l"(b)); return r;
}
__device__ __forceinline__ uint64_t sub2(uint64_t a, uint64_t b) {
    uint64_t r; asm("sub.rn.f32x2 %0, %1, %2;" : "=l"(r) : "l"(a), "l"(b)); return r;
}
__device__ __forceinline__ float tanh_ap(float x) {
    float r; asm("tanh.approx.f32 %0, %1;" : "=f"(r) : "f"(x)); return r;
}

__global__ __launch_bounds__(THREADS, 1)
void tiny_gru10_kernel(const float* __restrict__ in,     // (B,T,I)
                       const float* __restrict__ W_in,   // (I,3H)
                       const float* __restrict__ W_h,    // (H,3H)
                       const float* __restrict__ bias,   // (6H,)
                       const float* __restrict__ dec_W,  // (H,O)
                       const float* __restrict__ dec_b,  // (O,)
                       float* __restrict__ out)          // (B,T,O)
{
    __shared__ float sx[CHUNK * 3 * 33];   // [s = t*3+i][elem]
    __shared__ float so[CHUNK * 2 * 33];   // [s = t*2+o][elem]

    const int lane = threadIdx.x;
    const int b0   = blockIdx.x * THREADS;

    // Gate column order: c = gate*4 + unit; packed pairs p=0..5 cover columns
    // (2p, 2p+1): p=0,1 -> r0..3 ; p=2,3 -> z0..3 ; p=4,5 -> n0..3.
    // Folding: r,z scaled 0.5 (sigmoid(x)=0.5+0.5*tanh(x/2)), biases(in+h)
    // in the f-root. n: input side unscaled (b_in in f-root); recurrent side
    // scaled 0.5 with 0.5*b_h as g-root, so r*g_n = G2 + tr*G2.
    uint64_t wip[6][3], whp[6][4], bfp[6], bh2p[2];
#pragma unroll
    for (int p = 0; p < 6; p++) {
        const int c = 2 * p;
        const float s = (p < 4) ? 0.5f : 1.0f;
#pragma unroll
        for (int i = 0; i < 3; i++)
            wip[p][i] = pk2(W_in[i * 12 + c] * s, W_in[i * 12 + c + 1] * s);
#pragma unroll
        for (int j = 0; j < 4; j++)
            whp[p][j] = pk2(W_h[j * 12 + c] * 0.5f, W_h[j * 12 + c + 1] * 0.5f);
        if (p < 4)
            bfp[p] = pk2(0.5f * (bias[c] + bias[12 + c]),
                         0.5f * (bias[c + 1] + bias[12 + c + 1]));
        else
            bfp[p] = pk2(bias[c], bias[c + 1]);
    }
    bh2p[0] = pk2(0.5f * bias[12 + 8], 0.5f * bias[12 + 9]);
    bh2p[1] = pk2(0.5f * bias[12 + 10], 0.5f * bias[12 + 11]);

    uint64_t dwp[4], dbp;
#pragma unroll
    for (int j = 0; j < 4; j++) dwp[j] = pk2(dec_W[j * 2 + 0], dec_W[j * 2 + 1]);
    dbp = pk2(dec_b[0], dec_b[1]);
    const uint64_t half2 = pk2(0.5f, 0.5f);

    // state: h broadcast packs {h_j,h_j} (for g + decoder) and pair packs
    // {h0,h1},{h2,h3} (for the update)
    uint64_t hb[4], hq[2];
#pragma unroll
    for (int j = 0; j < 4; j++) hb[j] = 0;
    hq[0] = 0; hq[1] = 0;

    const float* inb  = in  + (size_t)b0 * TT * 3;
    float*       outb = out + (size_t)b0 * TT * 2;

    for (int tc = 0; tc < TT; tc += CHUNK) {
        // ---- stage input tile: coalesced LDG -> transposed smem ----
#pragma unroll 8
        for (int idx = lane; idx < THREADS * CHUNK * 3; idx += THREADS) {
            int r = idx / (CHUNK * 3);
            int s = idx - r * (CHUNK * 3);
            sx[s * 33 + r] = inb[(size_t)r * TT * 3 + tc * 3 + s];
        }
        __syncwarp();

        // ---- recurrence: packed gate math, no shuffles ----
#pragma unroll 4
        for (int tt = 0; tt < CHUNK; tt++) {
            float x0 = sx[(tt * 3 + 0) * 33 + lane];
            float x1 = sx[(tt * 3 + 1) * 33 + lane];
            float x2 = sx[(tt * 3 + 2) * 33 + lane];
            uint64_t xp0 = pk2(x0, x0), xp1 = pk2(x1, x1), xp2 = pk2(x2, x2);

            // f: input contributions, 6 packed (18 FMA2)
            uint64_t fp[6];
#pragma unroll
            for (int p = 0; p < 6; p++)
                fp[p] = fma2(xp2, wip[p][2], fma2(xp1, wip[p][1], fma2(xp0, wip[p][0], bfp[p])));

            // g: recurrent contributions (24 FMA2); r,z rooted at f, n at 0.5*b_h
            uint64_t gp[6];
#pragma unroll
            for (int p = 0; p < 6; p++) {
                uint64_t root = (p < 4) ? fp[p] : bh2p[p - 4];
                gp[p] = fma2(hb[3], whp[p][3], fma2(hb[2], whp[p][2],
                        fma2(hb[1], whp[p][1], fma2(hb[0], whp[p][0], root))));
            }

            // r,z activations
            float sr0, sr1, sr2, sr3, sz0, sz1, sz2, sz3;
            upk2(sr0, sr1, gp[0]); upk2(sr2, sr3, gp[1]);
            upk2(sz0, sz1, gp[2]); upk2(sz2, sz3, gp[3]);
            float tr0 = tanh_ap(sr0), tr1 = tanh_ap(sr1);
            float tr2 = tanh_ap(sr2), tr3 = tanh_ap(sr3);
            float tz0 = tanh_ap(sz0), tz1 = tanh_ap(sz1);
            float tz2 = tanh_ap(sz2), tz3 = tanh_ap(sz3);

            // n pre-activation: xn = f_n + G2 + tr*G2  (G2 = gp[4..5])
            uint64_t trp0 = pk2(tr0, tr1), trp1 = pk2(tr2, tr3);
            uint64_t xnp0 = fma2(trp0, gp[4], add2(fp[4], gp[4]));
            uint64_t xnp1 = fma2(trp1, gp[5], add2(fp[5], gp[5]));
            float xn0, xn1, xn2, xn3;
            upk2(xn0, xn1, xnp0); upk2(xn2, xn3, xnp1);
            float n0 = tanh_ap(xn0), n1 = tanh_ap(xn1);
            float n2 = tanh_ap(xn2), n3 = tanh_ap(xn3);

            // update: hn = n + (0.5 + 0.5*tz) * (h - n), packed in unit pairs
            uint64_t np0 = pk2(n0, n1), np1 = pk2(n2, n3);
            uint64_t Zp0 = fma2(pk2(tz0, tz1), half2, half2);
            uint64_t Zp1 = fma2(pk2(tz2, tz3), half2, half2);
            uint64_t hn0 = fma2(Zp0, sub2(hq[0], np0), np0);
            uint64_t hn1 = fma2(Zp1, sub2(hq[1], np1), np1);
            hq[0] = hn0; hq[1] = hn1;

            // rebuild broadcast packs for next step's g + this step's decoder
            float h0, h1, h2, h3;
            upk2(h0, h1, hn0); upk2(h2, h3, hn1);
            hb[0] = pk2(h0, h0); hb[1] = pk2(h1, h1);
            hb[2] = pk2(h2, h2); hb[3] = pk2(h3, h3);

            // decoder: {p0,p1} packed (4 FMA2), store both scalars
            uint64_t pp = fma2(hb[3], dwp[3], fma2(hb[2], dwp[2],
                          fma2(hb[1], dwp[1], fma2(hb[0], dwp[0], dbp))));
            float p0, p1;
            upk2(p0, p1, pp);
            so[(tt * 2 + 0) * 33 + lane] = p0;
            so[(tt * 2 + 1) * 33 + lane] = p1;
        }
        __syncwarp();

        // ---- write output tile: transposed smem -> coalesced STG ----
#pragma unroll 8
        for (int idx = lane; idx < THREADS * CHUNK * 2; idx += THREADS) {
            int r = idx / (CHUNK * 2);
            int s = idx - r * (CHUNK * 2);
            outb[(size_t)r * TT * 2 + tc * 2 + s] = so[s * 33 + r];
        }
        __syncwarp();   // so/sx reused next tile
    }
}

extern "C" void kernel_launch(void* const* d_in, const int* in_sizes, int n_in,
                              void* d_out, int out_size) {
    const float* in    = (const float*)d_in[0];
    const float* W_in  = (const float*)d_in[1];
    const float* W_h   = (const float*)d_in[2];
    const float* bias  = (const float*)d_in[3];
    const float* dec_W = (const float*)d_in[4];
    const float* dec_b = (const float*)d_in[5];
    float* out = (float*)d_out;

    tiny_gru10_kernel<<<BB / THREADS, THREADS>>>(in, W_in, W_h, bias, dec_W, dec_b, out);
}

// round 15
// speedup vs baseline: 2.9427x; 2.9427x over previous
#include <cuda_runtime.h>
#include <cuda_bf16.h>
#include <cstdint>

// TinyRNN (GRU): B=4096, T=2048, I=3, H=4, O=2
// Validated R9 shape (4 lanes/element, k=2 elements/thread, 128 blk x 64 thr)
// with the serial loop stripped to gates only:
//  - decoder + output stores moved to a per-tile epilogue (h history in smem)
//  - x fetched as 3x LDS.128 per 4-step group (natural prefetch)
//  - outputs written directly with STG.64 from the epilogue (no so buffer)

#define BB 4096
#define TT 2048
#define CHUNK 16
#define EPB 32               // elements per block
#define KK 2                 // elements per thread
#define THREADS 64
#define SXS 52               // sx row stride in floats (CHUNK*3 + 4), 16B-aligned
#define SHROW 132            // sh row stride in floats (EPB*4 + 4), 16B-aligned

__device__ __forceinline__ float tanh_ap(float x) {
    float r;
    asm("tanh.approx.f32 %0, %1;" : "=f"(r) : "f"(x));
    return r;
}

__global__ __launch_bounds__(THREADS, 1)
void tiny_gru15_kernel(const float* __restrict__ in,     // (B,T,I)
                       const float* __restrict__ W_in,   // (I,3H)
                       const float* __restrict__ W_h,    // (H,3H)
                       const float* __restrict__ bias,   // (6H,)
                       const float* __restrict__ dec_W,  // (H,O)
                       const float* __restrict__ dec_b,  // (O,)
                       float* __restrict__ out)          // (B,T,O)
{
    __shared__ float sx[EPB * SXS];       // staged inputs [elem][CHUNK*3]
    __shared__ float sh[CHUNK * SHROW];   // h history [step][elem*4+unit]

    const int tid   = threadIdx.x;
    const int u     = tid & 3;            // hidden unit
    const int gbase = tid >> 2;           // lane-group id (0..15)
    const int b0    = blockIdx.x * EPB;

    // ---- weight folding (validated in R5/R9) ----
    // r,z: sigmoid(x)=0.5+0.5*tanh(x/2) -> weights & (b_in+b_h) scaled by 0.5
    // n:   tanh direct; recurrent side scaled 0.5 so r*g_n = G2 + tanh(s_r)*G2
    float wiu[3][3];
#pragma unroll
    for (int g = 0; g < 3; g++) {
        float s = (g == 2) ? 1.0f : 0.5f;
#pragma unroll
        for (int i = 0; i < 3; i++) wiu[g][i] = W_in[i * 12 + g * 4 + u] * s;
    }
    // xor-permuted recurrent weights: whx[g][m] multiplies h_{u^m}
    float whx[3][4];
#pragma unroll
    for (int g = 0; g < 3; g++)
#pragma unroll
        for (int m = 0; m < 4; m++)
            whx[g][m] = W_h[(u ^ m) * 12 + g * 4 + u] * 0.5f;

    float bfu0 = 0.5f * (bias[0 + u] + bias[12 + u]);
    float bfu1 = 0.5f * (bias[4 + u] + bias[16 + u]);
    float bfu2 = bias[8 + u];
    float bh2u = 0.5f * bias[20 + u];

    // decoder weights, both output slots (epilogue only)
    float dw0[4], dw1[4], db0, db1;
#pragma unroll
    for (int j = 0; j < 4; j++) { dw0[j] = dec_W[j * 2 + 0]; dw1[j] = dec_W[j * 2 + 1]; }
    db0 = dec_b[0]; db1 = dec_b[1];

    // recurrent state: own h + 3 xor-neighbors, per element
    float hp[KK], hx1[KK], hx2[KK], hx3[KK];
#pragma unroll
    for (int j = 0; j < KK; j++) { hp[j] = hx1[j] = hx2[j] = hx3[j] = 0.0f; }

    const float* inb  = in  + (size_t)b0 * TT * 3;
    float*       outb = out + (size_t)b0 * TT * 2;

    const float* xb[KK];
    int          shb[KK];
#pragma unroll
    for (int j = 0; j < KK; j++) {
        xb[j]  = &sx[(gbase + 16 * j) * SXS];
        shb[j] = (gbase + 16 * j) * 4 + u;
    }

    for (int tc = 0; tc < TT; tc += CHUNK) {
        // ---- stage input tile: coalesced float4 LDG -> smem ----
#pragma unroll
        for (int m = 0; m < 6; m++) {
            int idx = tid + m * THREADS;          // 0..383
            int r   = idx / 12;                   // element 0..31
            int s4  = idx - r * 12;               // float4 index 0..11
            float4 v = *(const float4*)(inb + (size_t)r * TT * 3 + tc * 3 + s4 * 4);
            *(float4*)&sx[r * SXS + s4 * 4] = v;
        }
        __syncthreads();

        // ---- recurrence: 4 groups of 4 steps; x batch-loaded per group ----
#pragma unroll
        for (int q = 0; q < 4; q++) {
            // 12 floats (4 steps of x) per element via 3x LDS.128
            float xr[KK][12];
#pragma unroll
            for (int j = 0; j < KK; j++) {
                float4 a = *(const float4*)(xb[j] + q * 12 + 0);
                float4 b = *(const float4*)(xb[j] + q * 12 + 4);
                float4 c = *(const float4*)(xb[j] + q * 12 + 8);
                xr[j][0] = a.x; xr[j][1]  = a.y; xr[j][2]  = a.z; xr[j][3]  = a.w;
                xr[j][4] = b.x; xr[j][5]  = b.y; xr[j][6]  = b.z; xr[j][7]  = b.w;
                xr[j][8] = c.x; xr[j][9]  = c.y; xr[j][10] = c.z; xr[j][11] = c.w;
            }
#pragma unroll
            for (int s = 0; s < 4; s++) {
                const int tt = q * 4 + s;
#pragma unroll
                for (int j = 0; j < KK; j++) {
                    float x0 = xr[j][s * 3 + 0];
                    float x1 = xr[j][s * 3 + 1];
                    float x2 = xr[j][s * 3 + 2];

                    // input contributions (register-only, off the chain)
                    float f0 = fmaf(x2, wiu[0][2], fmaf(x1, wiu[0][1], fmaf(x0, wiu[0][0], bfu0)));
                    float f1 = fmaf(x2, wiu[1][2], fmaf(x1, wiu[1][1], fmaf(x0, wiu[1][0], bfu1)));
                    float f2 = fmaf(x2, wiu[2][2], fmaf(x1, wiu[2][1], fmaf(x0, wiu[2][0], bfu2)));

                    // recurrent chains: own h (hp) + xor-neighbors
                    float ga0 = fmaf(hx1[j], whx[0][1], fmaf(hp[j], whx[0][0], f0));
                    float gb0 = fmaf(hx3[j], whx[0][3], hx2[j] * whx[0][2]);
                    float ga1 = fmaf(hx1[j], whx[1][1], fmaf(hp[j], whx[1][0], f1));
                    float gb1 = fmaf(hx3[j], whx[1][3], hx2[j] * whx[1][2]);
                    float ga2 = fmaf(hx1[j], whx[2][1], fmaf(hp[j], whx[2][0], bh2u));
                    float gb2 = fmaf(hx3[j], whx[2][3], hx2[j] * whx[2][2]);

                    float tr = tanh_ap(ga0 + gb0);        // r = 0.5 + 0.5*tr
                    float tz = tanh_ap(ga1 + gb1);        // z = 0.5 + 0.5*tz
                    float G2 = ga2 + gb2;                 // 0.5 * g_n
                    float n_ = tanh_ap(fmaf(tr, G2, f2 + G2));

                    float Z  = fmaf(0.5f, tz, 0.5f);      // off-chain
                    float d  = hp[j] - n_;
                    float hn = fmaf(Z, d, n_);            // (1-z)n + z*h
                    hp[j] = hn;

                    hx1[j] = __shfl_xor_sync(0xffffffffu, hn, 1, 4);
                    hx2[j] = __shfl_xor_sync(0xffffffffu, hn, 2, 4);
                    hx3[j] = __shfl_xor_sync(0xffffffffu, hn, 3, 4);

                    sh[tt * SHROW + shb[j]] = hn;         // unconditional STS.32
                }
            }
        }
        __syncthreads();

        // ---- epilogue: decoder + direct STG.64 (off the serial path) ----
#pragma unroll
        for (int p = 0; p < 8; p++) {
            int idx = tid + p * THREADS;          // 0..511
            int r   = idx >> 4;                   // element 0..31
            int t   = idx & 15;                   // step within tile
            float4 hv = *(const float4*)&sh[t * SHROW + r * 4];
            float p0 = fmaf(hv.w, dw0[3], fmaf(hv.z, dw0[2],
                       fmaf(hv.y, dw0[1], fmaf(hv.x, dw0[0], db0))));
            float p1 = fmaf(hv.w, dw1[3], fmaf(hv.z, dw1[2],
                       fmaf(hv.y, dw1[1], fmaf(hv.x, dw1[0], db1))));
            *(float2*)(outb + (size_t)r * TT * 2 + (tc + t) * 2) = make_float2(p0, p1);
        }
        __syncthreads();   // sh/sx reused next tile
    }
}

extern "C" void kernel_launch(void* const* d_in, const int* in_sizes, int n_in,
                              void* d_out, int out_size) {
    const float* in    = (const float*)d_in[0];
    const float* W_in  = (const float*)d_in[1];
    const float* W_h   = (const float*)d_in[2];
    const float* bias  = (const float*)d_in[3];
    const float* dec_W = (const float*)d_in[4];
    const float* dec_b = (const float*)d_in[5];
    float* out = (float*)d_out;

    tiny_gru15_kernel<<<BB / EPB, THREADS>>>(in, W_in, W_h, bias, dec_W, dec_b, out);
}